// round 3
// baseline (speedup 1.0000x reference)
#include <cuda_runtime.h>
#include <cstdint>

#define N_NODES 4096
#define N_EDGES 131072

using u64 = unsigned long long;

// ---------------- scratch (device globals) ----------------------------------
__device__ int   g_counts[N_NODES];
__device__ int   g_offsets[N_NODES + 1];
__device__ int   g_cursor[N_NODES];
__device__ int   g_rank[N_EDGES];
__device__ float g_x1[N_NODES * 36];
__device__ float g_x2[N_NODES * 24];
__device__ float g_x3[N_NODES * 8];
__device__ float g_msg[N_EDGES * 36];   // reused per layer

// ---------------- f32x2 helpers ----------------------------------------------
__device__ __forceinline__ u64 pack2(float x, float y) {
    u64 r; asm("mov.b64 %0, {%1,%2};" : "=l"(r) : "f"(x), "f"(y)); return r;
}
__device__ __forceinline__ void unpack2(u64 v, float& x, float& y) {
    asm("mov.b64 {%0,%1}, %2;" : "=f"(x), "=f"(y) : "l"(v));
}
__device__ __forceinline__ u64 fma2(u64 a, u64 b, u64 c) {
    u64 d; asm("fma.rn.f32x2 %0, %1, %2, %3;" : "=l"(d) : "l"(a), "l"(b), "l"(c)); return d;
}
__device__ __forceinline__ void lds2(u64& A, u64& B, uint32_t addr) {
    asm volatile("ld.shared.v2.b64 {%0,%1}, [%2];" : "=l"(A), "=l"(B) : "r"(addr));
}
__device__ __forceinline__ uint32_t smem_u32(const void* p) {
    uint32_t a;
    asm("{ .reg .u64 t; cvta.to.shared.u64 t, %1; cvt.u32.u64 %0, t; }" : "=r"(a) : "l"(p));
    return a;
}

// ---------------- counting sort by dst ---------------------------------------
__global__ void zero_counts_kernel(int* __restrict__ c) {
    int i = blockIdx.x * blockDim.x + threadIdx.x;
    if (i < N_NODES) c[i] = 0;
}

__global__ void hist_kernel(const int* __restrict__ dst, int* __restrict__ c) {
    int e = blockIdx.x * blockDim.x + threadIdx.x;
    if (e < N_EDGES) atomicAdd(&c[dst[e]], 1);
}

// single block, 1024 threads, 4 elems each -> exclusive scan of 4096 counts
__global__ void scan_kernel(const int* __restrict__ c,
                            int* __restrict__ off, int* __restrict__ cur) {
    __shared__ int s[1024];
    int t = threadIdx.x;
    int c0 = c[4 * t], c1 = c[4 * t + 1], c2 = c[4 * t + 2], c3 = c[4 * t + 3];
    int sum = c0 + c1 + c2 + c3;
    s[t] = sum;
    __syncthreads();
    for (int d = 1; d < 1024; d <<= 1) {
        int v = (t >= d) ? s[t - d] : 0;
        __syncthreads();
        s[t] += v;
        __syncthreads();
    }
    int base = (t > 0) ? s[t - 1] : 0;
    off[4 * t] = base;               cur[4 * t] = base;
    off[4 * t + 1] = base + c0;      cur[4 * t + 1] = base + c0;
    off[4 * t + 2] = base + c0 + c1; cur[4 * t + 2] = base + c0 + c1;
    off[4 * t + 3] = base + c0 + c1 + c2; cur[4 * t + 3] = base + c0 + c1 + c2;
    if (t == 1023) off[N_NODES] = s[1023];
}

__global__ void rank_kernel(const int* __restrict__ dst,
                            int* __restrict__ cur, int* __restrict__ rank) {
    int e = blockIdx.x * blockDim.x + threadIdx.x;
    if (e < N_EDGES) rank[e] = atomicAdd(&cur[dst[e]], 1);
}

// ---------------- edge kernels (packed f32x2) --------------------------------
// msg[rank[e], o] = sum_i x[src,i] * relu(sum_v a_v W[v,i,o] + b[i,o])
template <int DIN, int DOUT>
__global__ void __launch_bounds__(256) edge_kernel(
    const float* __restrict__ x, const float* __restrict__ ea,
    const int* __restrict__ src, const int* __restrict__ rank,
    const float* __restrict__ w, const float* __restrict__ b,
    float* __restrict__ msg)
{
    static_assert(DOUT % 4 == 0, "DOUT multiple of 4");
    constexpr int PLANE = DIN * DOUT * 4;         // bytes per view plane
    __shared__ __align__(16) float sW[7 * DIN * DOUT];
    {
        float4* s4 = reinterpret_cast<float4*>(sW);
        const float4* w4 = reinterpret_cast<const float4*>(w);
        const float4* b4 = reinterpret_cast<const float4*>(b);
        const int nw4 = (6 * DIN * DOUT) / 4;
        const int nb4 = (DIN * DOUT) / 4;
        for (int i = threadIdx.x; i < nw4; i += blockDim.x) s4[i] = w4[i];
        for (int i = threadIdx.x; i < nb4; i += blockDim.x) s4[nw4 + i] = b4[i];
    }
    __syncthreads();
    const uint32_t sbase = smem_u32(sW);

    int e = blockIdx.x * 256 + threadIdx.x;

    const float2* ea2 = reinterpret_cast<const float2*>(ea + e * 6);
    float2 p0 = ea2[0], p1 = ea2[1], p2 = ea2[2];
    u64 av[6];
    av[0] = pack2(p0.x, p0.x); av[1] = pack2(p0.y, p0.y);
    av[2] = pack2(p1.x, p1.x); av[3] = pack2(p1.y, p1.y);
    av[4] = pack2(p2.x, p2.x); av[5] = pack2(p2.y, p2.y);

    const int s = src[e];
    const float* __restrict__ xs = x + s * DIN;

    float acc[DOUT];
#pragma unroll
    for (int o = 0; o < DOUT; o++) acc[o] = 0.0f;

#pragma unroll
    for (int i = 0; i < DIN; i++) {
        const float xi = xs[i];
#pragma unroll
        for (int g = 0; g < DOUT / 4; g++) {
            uint32_t ra = sbase + (i * DOUT + 4 * g) * 4;
            u64 v0, v1, wA, wB;
            lds2(v0, v1, ra + 6 * PLANE);                 // bias pair
#pragma unroll
            for (int k = 0; k < 6; k++) {
                lds2(wA, wB, ra + k * PLANE);
                v0 = fma2(av[k], wA, v0);
                v1 = fma2(av[k], wB, v1);
            }
            float f0, f1, f2, f3;
            unpack2(v0, f0, f1);
            unpack2(v1, f2, f3);
            acc[4 * g + 0] = fmaf(xi, fmaxf(f0, 0.0f), acc[4 * g + 0]);
            acc[4 * g + 1] = fmaf(xi, fmaxf(f1, 0.0f), acc[4 * g + 1]);
            acc[4 * g + 2] = fmaf(xi, fmaxf(f2, 0.0f), acc[4 * g + 2]);
            acc[4 * g + 3] = fmaf(xi, fmaxf(f3, 0.0f), acc[4 * g + 3]);
        }
    }

    const int r = rank[e];
    float4* m4 = reinterpret_cast<float4*>(msg + (size_t)r * DOUT);
#pragma unroll
    for (int g = 0; g < DOUT / 4; g++) {
        float4 rv;
        rv.x = acc[4 * g + 0]; rv.y = acc[4 * g + 1];
        rv.z = acc[4 * g + 2]; rv.w = acc[4 * g + 3];
        m4[g] = rv;
    }
}

// layer 3 variant: DOUT=5 (scalar)
__global__ void __launch_bounds__(256) edge_kernel_l3(
    const float* __restrict__ x, const float* __restrict__ ea,
    const int* __restrict__ src, const int* __restrict__ rank,
    const float* __restrict__ w, const float* __restrict__ b,
    float* __restrict__ msg)
{
    const int DIN = 24, DOUT = 5;
    __shared__ __align__(16) float sW[7 * DIN * DOUT];
    {
        float4* s4 = reinterpret_cast<float4*>(sW);
        const float4* w4 = reinterpret_cast<const float4*>(w);
        const float4* b4 = reinterpret_cast<const float4*>(b);
        for (int i = threadIdx.x; i < (6 * DIN * DOUT) / 4; i += blockDim.x) s4[i] = w4[i];
        for (int i = threadIdx.x; i < (DIN * DOUT) / 4; i += blockDim.x)
            s4[(6 * DIN * DOUT) / 4 + i] = b4[i];
    }
    __syncthreads();
    const float* sB = sW + 6 * DIN * DOUT;

    int e = blockIdx.x * 256 + threadIdx.x;
    const float2* ea2 = reinterpret_cast<const float2*>(ea + e * 6);
    float2 p0 = ea2[0], p1 = ea2[1], p2 = ea2[2];
    const float a0 = p0.x, a1 = p0.y, a2 = p1.x, a3 = p1.y, a4 = p2.x, a5 = p2.y;
    const int s = src[e];
    const float* __restrict__ xs = x + s * DIN;

    float acc[DOUT];
#pragma unroll
    for (int o = 0; o < DOUT; o++) acc[o] = 0.0f;
#pragma unroll
    for (int i = 0; i < DIN; i++) {
        const float xi = xs[i];
#pragma unroll
        for (int o = 0; o < DOUT; o++) {
            float v = sB[i * DOUT + o];
            v = fmaf(a0, sW[0 * DIN * DOUT + i * DOUT + o], v);
            v = fmaf(a1, sW[1 * DIN * DOUT + i * DOUT + o], v);
            v = fmaf(a2, sW[2 * DIN * DOUT + i * DOUT + o], v);
            v = fmaf(a3, sW[3 * DIN * DOUT + i * DOUT + o], v);
            v = fmaf(a4, sW[4 * DIN * DOUT + i * DOUT + o], v);
            v = fmaf(a5, sW[5 * DIN * DOUT + i * DOUT + o], v);
            acc[o] = fmaf(xi, fmaxf(v, 0.0f), acc[o]);
        }
    }
    const int r = rank[e];
#pragma unroll
    for (int o = 0; o < DOUT; o++) msg[(size_t)r * DOUT + o] = acc[o];
}

// ---------------- aggregation: contiguous CSR rows + root + relu -------------
template <int DIN, int DOUT>
__global__ void __launch_bounds__(256) agg_kernel(
    const float* __restrict__ msg, const int* __restrict__ off,
    const float* __restrict__ xin, const float* __restrict__ lin,
    const float* __restrict__ bias, float* __restrict__ xout)
{
    int idx = blockIdx.x * 256 + threadIdx.x;
    if (idx >= N_NODES * DOUT) return;
    int n = idx / DOUT;
    int o = idx - n * DOUT;
    int s = off[n], epos = off[n + 1];
    float acc = 0.0f;
    for (int j = s; j < epos; j++) acc += msg[(size_t)j * DOUT + o];
    float deg = fmaxf((float)(epos - s), 1.0f);
    float v = acc / deg + bias[o];
    const float* __restrict__ xr = xin + n * DIN;
    const float* __restrict__ lr = lin + o * DIN;
#pragma unroll
    for (int i = 0; i < DIN; i++) v = fmaf(xr[i], lr[i], v);
    xout[n * DOUT + o] = fmaxf(v, 0.0f);
}

// ---------------- pairwise abs-diff ------------------------------------------
__global__ void __launch_bounds__(256) cbt_kernel(
    const float* __restrict__ x3, float* __restrict__ out)
{
    __shared__ float sa[16 * 5];
    int bcol = blockIdx.x * 256 + threadIdx.x;
    int a0 = blockIdx.y * 16;
    if (threadIdx.x < 80) sa[threadIdx.x] = x3[a0 * 5 + threadIdx.x];
    __syncthreads();

    const float b0 = x3[bcol * 5 + 0];
    const float b1 = x3[bcol * 5 + 1];
    const float b2 = x3[bcol * 5 + 2];
    const float b3 = x3[bcol * 5 + 3];
    const float b4 = x3[bcol * 5 + 4];

#pragma unroll
    for (int j = 0; j < 16; j++) {
        float s = fabsf(b0 - sa[j * 5 + 0])
                + fabsf(b1 - sa[j * 5 + 1])
                + fabsf(b2 - sa[j * 5 + 2])
                + fabsf(b3 - sa[j * 5 + 3])
                + fabsf(b4 - sa[j * 5 + 4]);
        out[(size_t)(a0 + j) * N_NODES + bcol] = s;
    }
}

// ---------------- launcher ----------------------------------------------------
extern "C" void kernel_launch(void* const* d_in, const int* in_sizes, int n_in,
                              void* d_out, int out_size)
{
    const float* x0  = (const float*)d_in[0];
    const float* ea  = (const float*)d_in[1];
    const int*   ei  = (const int*)  d_in[2];
    const int*   src = ei;
    const int*   dst = ei + N_EDGES;

    const float* w1  = (const float*)d_in[3];
    const float* bn1 = (const float*)d_in[4];
    const float* l1  = (const float*)d_in[5];
    const float* bi1 = (const float*)d_in[6];
    const float* w2  = (const float*)d_in[7];
    const float* bn2 = (const float*)d_in[8];
    const float* l2  = (const float*)d_in[9];
    const float* bi2 = (const float*)d_in[10];
    const float* w3  = (const float*)d_in[11];
    const float* bn3 = (const float*)d_in[12];
    const float* l3  = (const float*)d_in[13];
    const float* bi3 = (const float*)d_in[14];

    int *counts, *offs, *cur, *rank;
    float *x1, *x2, *x3, *msg;
    cudaGetSymbolAddress((void**)&counts, g_counts);
    cudaGetSymbolAddress((void**)&offs,   g_offsets);
    cudaGetSymbolAddress((void**)&cur,    g_cursor);
    cudaGetSymbolAddress((void**)&rank,   g_rank);
    cudaGetSymbolAddress((void**)&x1,     g_x1);
    cudaGetSymbolAddress((void**)&x2,     g_x2);
    cudaGetSymbolAddress((void**)&x3,     g_x3);
    cudaGetSymbolAddress((void**)&msg,    g_msg);

    float* out = (float*)d_out;

    // counting sort of edges by dst -> offsets + rank
    zero_counts_kernel<<<N_NODES / 256, 256>>>(counts);
    hist_kernel<<<N_EDGES / 256, 256>>>(dst, counts);
    scan_kernel<<<1, 1024>>>(counts, offs, cur);
    rank_kernel<<<N_EDGES / 256, 256>>>(dst, cur, rank);

    // layer 1: 1 -> 36
    edge_kernel<1, 36><<<N_EDGES / 256, 256>>>(x0, ea, src, rank, w1, bn1, msg);
    agg_kernel<1, 36><<<(N_NODES * 36) / 256, 256>>>(msg, offs, x0, l1, bi1, x1);

    // layer 2: 36 -> 24
    edge_kernel<36, 24><<<N_EDGES / 256, 256>>>(x1, ea, src, rank, w2, bn2, msg);
    agg_kernel<36, 24><<<(N_NODES * 24) / 256, 256>>>(msg, offs, x1, l2, bi2, x2);

    // layer 3: 24 -> 5
    edge_kernel_l3<<<N_EDGES / 256, 256>>>(x2, ea, src, rank, w3, bn3, msg);
    agg_kernel<24, 5><<<(N_NODES * 5) / 256, 256>>>(msg, offs, x2, l3, bi3, x3);

    // pairwise L1 distance matrix
    dim3 cgrid(N_NODES / 256, N_NODES / 16);
    cbt_kernel<<<cgrid, 256>>>(x3, out);
}

// round 4
// speedup vs baseline: 1.0914x; 1.0914x over previous
#include <cuda_runtime.h>
#include <cstdint>

#define N_NODES 4096
#define N_EDGES 131072

// ---------------- scratch (device globals) ----------------------------------
__device__ int   g_counts[N_NODES];
__device__ int   g_offsets[N_NODES + 1];
__device__ int   g_lrank[N_EDGES];
__device__ float g_x1[N_NODES * 36];
__device__ float g_x2[N_NODES * 24];
__device__ float g_x3[N_NODES * 8];
__device__ float g_msg[N_EDGES * 36];   // reused per layer

// ---------------- counting sort by dst ---------------------------------------
__global__ void zero_counts_kernel(int* __restrict__ c) {
    int i = blockIdx.x * blockDim.x + threadIdx.x;
    if (i < N_NODES) c[i] = 0;
}

// histogram; atomic return value = within-node local rank
__global__ void hist_kernel(const int* __restrict__ dst, int* __restrict__ c,
                            int* __restrict__ lrank) {
    int e = blockIdx.x * blockDim.x + threadIdx.x;
    if (e < N_EDGES) lrank[e] = atomicAdd(&c[dst[e]], 1);
}

// single block, 1024 threads, 4 elems each -> exclusive scan of 4096 counts
__global__ void scan_kernel(const int* __restrict__ c, int* __restrict__ off) {
    __shared__ int s[1024];
    int t = threadIdx.x;
    int c0 = c[4 * t], c1 = c[4 * t + 1], c2 = c[4 * t + 2], c3 = c[4 * t + 3];
    int sum = c0 + c1 + c2 + c3;
    s[t] = sum;
    __syncthreads();
    for (int d = 1; d < 1024; d <<= 1) {
        int v = (t >= d) ? s[t - d] : 0;
        __syncthreads();
        s[t] += v;
        __syncthreads();
    }
    int base = (t > 0) ? s[t - 1] : 0;
    off[4 * t] = base;
    off[4 * t + 1] = base + c0;
    off[4 * t + 2] = base + c0 + c1;
    off[4 * t + 3] = base + c0 + c1 + c2;
    if (t == 1023) off[N_NODES] = s[1023];
}

// ---------------- edge kernels: thread = edge, W via broadcast LDS.128 -------
// msg[off[dst]+lrank, o] = sum_i x[src,i] * relu(sum_v a_v W[v,i,o] + b[i,o])
template <int DIN, int DOUT>
__global__ void __launch_bounds__(256) edge_kernel(
    const float* __restrict__ x, const float* __restrict__ ea,
    const int* __restrict__ src, const int* __restrict__ dst,
    const int* __restrict__ lrank, const int* __restrict__ off,
    const float* __restrict__ w, const float* __restrict__ b,
    float* __restrict__ msg)
{
    __shared__ __align__(16) float sW[7 * DIN * DOUT];
    {
        float4* s4 = reinterpret_cast<float4*>(sW);
        const float4* w4 = reinterpret_cast<const float4*>(w);
        const float4* b4 = reinterpret_cast<const float4*>(b);
        const int nw4 = (6 * DIN * DOUT) / 4;
        const int nb4 = (DIN * DOUT) / 4;
        for (int i = threadIdx.x; i < nw4; i += blockDim.x) s4[i] = w4[i];
        for (int i = threadIdx.x; i < nb4; i += blockDim.x) s4[nw4 + i] = b4[i];
    }
    __syncthreads();
    const float4* sW4 = reinterpret_cast<const float4*>(sW);
    const float4* sB4 = reinterpret_cast<const float4*>(sW + 6 * DIN * DOUT);

    int e = blockIdx.x * 256 + threadIdx.x;

    const float2* ea2 = reinterpret_cast<const float2*>(ea + e * 6);
    float2 p0 = ea2[0], p1 = ea2[1], p2 = ea2[2];
    const float a0 = p0.x, a1 = p0.y, a2 = p1.x, a3 = p1.y, a4 = p2.x, a5 = p2.y;

    const int s = src[e];
    const int r = off[dst[e]] + lrank[e];
    const float* __restrict__ xs = x + s * DIN;

    float acc[DOUT];
#pragma unroll
    for (int o = 0; o < DOUT; o++) acc[o] = 0.0f;

    static_assert(DOUT % 4 == 0, "DOUT multiple of 4");
#pragma unroll
    for (int i = 0; i < DIN; i++) {
        const float xi = xs[i];
#pragma unroll
        for (int o4 = 0; o4 < DOUT / 4; o4++) {
            float4 wb = sB4[(i * DOUT) / 4 + o4];
            float4 w0 = sW4[(0 * DIN * DOUT + i * DOUT) / 4 + o4];
            float4 w1 = sW4[(1 * DIN * DOUT + i * DOUT) / 4 + o4];
            float4 w2 = sW4[(2 * DIN * DOUT + i * DOUT) / 4 + o4];
            float4 w3 = sW4[(3 * DIN * DOUT + i * DOUT) / 4 + o4];
            float4 w4v = sW4[(4 * DIN * DOUT + i * DOUT) / 4 + o4];
            float4 w5 = sW4[(5 * DIN * DOUT + i * DOUT) / 4 + o4];
            float v;
            v = wb.x; v = fmaf(a0, w0.x, v); v = fmaf(a1, w1.x, v); v = fmaf(a2, w2.x, v);
            v = fmaf(a3, w3.x, v); v = fmaf(a4, w4v.x, v); v = fmaf(a5, w5.x, v);
            acc[o4 * 4 + 0] = fmaf(xi, fmaxf(v, 0.0f), acc[o4 * 4 + 0]);
            v = wb.y; v = fmaf(a0, w0.y, v); v = fmaf(a1, w1.y, v); v = fmaf(a2, w2.y, v);
            v = fmaf(a3, w3.y, v); v = fmaf(a4, w4v.y, v); v = fmaf(a5, w5.y, v);
            acc[o4 * 4 + 1] = fmaf(xi, fmaxf(v, 0.0f), acc[o4 * 4 + 1]);
            v = wb.z; v = fmaf(a0, w0.z, v); v = fmaf(a1, w1.z, v); v = fmaf(a2, w2.z, v);
            v = fmaf(a3, w3.z, v); v = fmaf(a4, w4v.z, v); v = fmaf(a5, w5.z, v);
            acc[o4 * 4 + 2] = fmaf(xi, fmaxf(v, 0.0f), acc[o4 * 4 + 2]);
            v = wb.w; v = fmaf(a0, w0.w, v); v = fmaf(a1, w1.w, v); v = fmaf(a2, w2.w, v);
            v = fmaf(a3, w3.w, v); v = fmaf(a4, w4v.w, v); v = fmaf(a5, w5.w, v);
            acc[o4 * 4 + 3] = fmaf(xi, fmaxf(v, 0.0f), acc[o4 * 4 + 3]);
        }
    }

    float4* m4 = reinterpret_cast<float4*>(msg + (size_t)r * DOUT);
#pragma unroll
    for (int o4 = 0; o4 < DOUT / 4; o4++) {
        float4 rv;
        rv.x = acc[o4 * 4 + 0]; rv.y = acc[o4 * 4 + 1];
        rv.z = acc[o4 * 4 + 2]; rv.w = acc[o4 * 4 + 3];
        m4[o4] = rv;
    }
}

// layer 3 variant: DOUT=5 (scalar)
__global__ void __launch_bounds__(256) edge_kernel_l3(
    const float* __restrict__ x, const float* __restrict__ ea,
    const int* __restrict__ src, const int* __restrict__ dst,
    const int* __restrict__ lrank, const int* __restrict__ off,
    const float* __restrict__ w, const float* __restrict__ b,
    float* __restrict__ msg)
{
    const int DIN = 24, DOUT = 5;
    __shared__ __align__(16) float sW[7 * DIN * DOUT];
    {
        float4* s4 = reinterpret_cast<float4*>(sW);
        const float4* w4 = reinterpret_cast<const float4*>(w);
        const float4* b4 = reinterpret_cast<const float4*>(b);
        for (int i = threadIdx.x; i < (6 * DIN * DOUT) / 4; i += blockDim.x) s4[i] = w4[i];
        for (int i = threadIdx.x; i < (DIN * DOUT) / 4; i += blockDim.x)
            s4[(6 * DIN * DOUT) / 4 + i] = b4[i];
    }
    __syncthreads();
    const float* sB = sW + 6 * DIN * DOUT;

    int e = blockIdx.x * 256 + threadIdx.x;
    const float2* ea2 = reinterpret_cast<const float2*>(ea + e * 6);
    float2 p0 = ea2[0], p1 = ea2[1], p2 = ea2[2];
    const float a0 = p0.x, a1 = p0.y, a2 = p1.x, a3 = p1.y, a4 = p2.x, a5 = p2.y;
    const int s = src[e];
    const int r = off[dst[e]] + lrank[e];
    const float* __restrict__ xs = x + s * DIN;

    float acc[DOUT];
#pragma unroll
    for (int o = 0; o < DOUT; o++) acc[o] = 0.0f;
#pragma unroll
    for (int i = 0; i < DIN; i++) {
        const float xi = xs[i];
#pragma unroll
        for (int o = 0; o < DOUT; o++) {
            float v = sB[i * DOUT + o];
            v = fmaf(a0, sW[0 * DIN * DOUT + i * DOUT + o], v);
            v = fmaf(a1, sW[1 * DIN * DOUT + i * DOUT + o], v);
            v = fmaf(a2, sW[2 * DIN * DOUT + i * DOUT + o], v);
            v = fmaf(a3, sW[3 * DIN * DOUT + i * DOUT + o], v);
            v = fmaf(a4, sW[4 * DIN * DOUT + i * DOUT + o], v);
            v = fmaf(a5, sW[5 * DIN * DOUT + i * DOUT + o], v);
            acc[o] = fmaf(xi, fmaxf(v, 0.0f), acc[o]);
        }
    }
#pragma unroll
    for (int o = 0; o < DOUT; o++) msg[(size_t)r * DOUT + o] = acc[o];
}

// ---------------- aggregation: contiguous CSR rows + root + relu -------------
template <int DIN, int DOUT>
__global__ void __launch_bounds__(256) agg_kernel(
    const float* __restrict__ msg, const int* __restrict__ off,
    const float* __restrict__ xin, const float* __restrict__ lin,
    const float* __restrict__ bias, float* __restrict__ xout)
{
    int idx = blockIdx.x * 256 + threadIdx.x;
    if (idx >= N_NODES * DOUT) return;
    int n = idx / DOUT;
    int o = idx - n * DOUT;
    int s = off[n], epos = off[n + 1];
    float acc = 0.0f;
#pragma unroll 4
    for (int j = s; j < epos; j++) acc += __ldg(&msg[(size_t)j * DOUT + o]);
    float deg = fmaxf((float)(epos - s), 1.0f);
    float v = acc / deg + bias[o];
    const float* __restrict__ xr = xin + n * DIN;
    const float* __restrict__ lr = lin + o * DIN;
#pragma unroll
    for (int i = 0; i < DIN; i++) v = fmaf(xr[i], lr[i], v);
    xout[n * DOUT + o] = fmaxf(v, 0.0f);
}

// ---------------- pairwise abs-diff, float4 stores ---------------------------
// thread: 4 consecutive b-cols x 16 a-rows
__global__ void __launch_bounds__(256) cbt_kernel(
    const float* __restrict__ x3, float* __restrict__ out)
{
    __shared__ float sa[16 * 5];
    int t = threadIdx.x;
    int bcol = blockIdx.x * 1024 + t * 4;
    int a0 = blockIdx.y * 16;
    if (t < 80) sa[t] = x3[a0 * 5 + t];
    __syncthreads();

    float bf[4][5];
#pragma unroll
    for (int c = 0; c < 4; c++)
#pragma unroll
        for (int f = 0; f < 5; f++) bf[c][f] = x3[(bcol + c) * 5 + f];

#pragma unroll
    for (int j = 0; j < 16; j++) {
        float4 r;
        float a_0 = sa[j * 5 + 0], a_1 = sa[j * 5 + 1], a_2 = sa[j * 5 + 2];
        float a_3 = sa[j * 5 + 3], a_4 = sa[j * 5 + 4];
        r.x = fabsf(bf[0][0] - a_0) + fabsf(bf[0][1] - a_1) + fabsf(bf[0][2] - a_2)
            + fabsf(bf[0][3] - a_3) + fabsf(bf[0][4] - a_4);
        r.y = fabsf(bf[1][0] - a_0) + fabsf(bf[1][1] - a_1) + fabsf(bf[1][2] - a_2)
            + fabsf(bf[1][3] - a_3) + fabsf(bf[1][4] - a_4);
        r.z = fabsf(bf[2][0] - a_0) + fabsf(bf[2][1] - a_1) + fabsf(bf[2][2] - a_2)
            + fabsf(bf[2][3] - a_3) + fabsf(bf[2][4] - a_4);
        r.w = fabsf(bf[3][0] - a_0) + fabsf(bf[3][1] - a_1) + fabsf(bf[3][2] - a_2)
            + fabsf(bf[3][3] - a_3) + fabsf(bf[3][4] - a_4);
        *reinterpret_cast<float4*>(&out[(size_t)(a0 + j) * N_NODES + bcol]) = r;
    }
}

// ---------------- launcher ----------------------------------------------------
extern "C" void kernel_launch(void* const* d_in, const int* in_sizes, int n_in,
                              void* d_out, int out_size)
{
    const float* x0  = (const float*)d_in[0];
    const float* ea  = (const float*)d_in[1];
    const int*   ei  = (const int*)  d_in[2];
    const int*   src = ei;
    const int*   dst = ei + N_EDGES;

    const float* w1  = (const float*)d_in[3];
    const float* bn1 = (const float*)d_in[4];
    const float* l1  = (const float*)d_in[5];
    const float* bi1 = (const float*)d_in[6];
    const float* w2  = (const float*)d_in[7];
    const float* bn2 = (const float*)d_in[8];
    const float* l2  = (const float*)d_in[9];
    const float* bi2 = (const float*)d_in[10];
    const float* w3  = (const float*)d_in[11];
    const float* bn3 = (const float*)d_in[12];
    const float* l3  = (const float*)d_in[13];
    const float* bi3 = (const float*)d_in[14];

    int *counts, *offs, *lrank;
    float *x1, *x2, *x3, *msg;
    cudaGetSymbolAddress((void**)&counts, g_counts);
    cudaGetSymbolAddress((void**)&offs,   g_offsets);
    cudaGetSymbolAddress((void**)&lrank,  g_lrank);
    cudaGetSymbolAddress((void**)&x1,     g_x1);
    cudaGetSymbolAddress((void**)&x2,     g_x2);
    cudaGetSymbolAddress((void**)&x3,     g_x3);
    cudaGetSymbolAddress((void**)&msg,    g_msg);

    float* out = (float*)d_out;

    // counting sort of edges by dst -> offsets + local ranks (3 launches)
    zero_counts_kernel<<<N_NODES / 256, 256>>>(counts);
    hist_kernel<<<N_EDGES / 256, 256>>>(dst, counts, lrank);
    scan_kernel<<<1, 1024>>>(counts, offs);

    // layer 1: 1 -> 36                      (launches 4, 5)
    edge_kernel<1, 36><<<N_EDGES / 256, 256>>>(x0, ea, src, dst, lrank, offs, w1, bn1, msg);
    agg_kernel<1, 36><<<(N_NODES * 36) / 256, 256>>>(msg, offs, x0, l1, bi1, x1);

    // layer 2: 36 -> 24                     (launch 6 — ncu captures this one)
    edge_kernel<36, 24><<<N_EDGES / 256, 256>>>(x1, ea, src, dst, lrank, offs, w2, bn2, msg);
    agg_kernel<36, 24><<<(N_NODES * 24) / 256, 256>>>(msg, offs, x1, l2, bi2, x2);

    // layer 3: 24 -> 5
    edge_kernel_l3<<<N_EDGES / 256, 256>>>(x2, ea, src, dst, lrank, offs, w3, bn3, msg);
    agg_kernel<24, 5><<<(N_NODES * 5) / 256, 256>>>(msg, offs, x2, l3, bi3, x3);

    // pairwise L1 distance matrix
    dim3 cgrid(N_NODES / 1024, N_NODES / 16);
    cbt_kernel<<<cgrid, 256>>>(x3, out);
}